// round 6
// baseline (speedup 1.0000x reference)
#include <cuda_runtime.h>
#include <math.h>

#define D 8
#define HID 64
#define PTS_PER_CTA 4
#define THREADS 512
#define GRID 2048
#define EPSF 1e-4f
#define TWOEPSF 2e-4f

typedef unsigned long long u64;

__device__ __forceinline__ u64 pack2(float lo, float hi) {
    u64 r; asm("mov.b64 %0, {%1, %2};" : "=l"(r) : "f"(lo), "f"(hi)); return r;
}

// XLA EmitFastTanh (with_fma=true): verified bit-match with reference in R3.
__device__ __forceinline__ float xla_tanh(float x) {
    const float kClamp = 7.90531110763549805f;
    float xc = fminf(fmaxf(x, -kClamp), kClamp);
    float x2 = __fmul_rn(xc, xc);
    float num = -2.76076847742355e-16f;
    num = __fmaf_rn(x2, num,  2.00018790482477e-13f);
    num = __fmaf_rn(x2, num, -8.60467152213735e-11f);
    num = __fmaf_rn(x2, num,  5.12229709037114e-08f);
    num = __fmaf_rn(x2, num,  1.48572235717979e-05f);
    num = __fmaf_rn(x2, num,  6.37261928875436e-04f);
    num = __fmaf_rn(x2, num,  4.89352455891786e-03f);
    num = __fmul_rn(xc, num);
    float den = 1.19825839466702e-06f;
    den = __fmaf_rn(x2, den,  1.18534705686654e-04f);
    den = __fmaf_rn(x2, den,  2.26843463243900e-03f);
    den = __fmaf_rn(x2, den,  4.89352518554385e-03f);
    float r = __fdiv_rn(num, den);
    return (fabsf(x) < 0.0004f) ? x : r;
}

// smem float offsets (all float4-aligned)
#define OFF_W2  0                        // 32768
#define OFF_W1  (OFF_W2 + 32768)         // 512
#define OFF_B1  (OFF_W1 + 512)           // 64
#define OFF_B2  (OFF_B1 + 64)            // 512
#define OFF_G   (OFF_B2 + 512)           // 512
#define OFF_UV  (OFF_G + 512)            // 4*16 = 64
#define OFF_T2  (OFF_UV + 64)            // 4 pts * 64h * 8k * 2 = 4096
#define OFF_CP  (OFF_T2 + 4096)          // 4 pts * 544 = 2176 (i*68 padded)
#define OFF_CM  (OFF_CP + 2176)          // 2176
#define OFF_RED (OFF_CM + 2176)          // 16
#define SMEM_FLOATS (OFF_RED + 16)
#define SMEM_BYTES (SMEM_FLOATS * 4)

__global__ void __launch_bounds__(THREADS, 1)
rg_kernel(const float* __restrict__ pos, const float* __restrict__ uu_g,
          const float* __restrict__ vv_g, const float* __restrict__ chol,
          const float* __restrict__ W1,  const float* __restrict__ b1,
          const float* __restrict__ W2,  const float* __restrict__ b2,
          float* __restrict__ out)
{
    extern __shared__ float sm[];
    float* W2s = sm + OFF_W2;
    float* W1s = sm + OFF_W1;
    float* b1s = sm + OFF_B1;
    float* b2s = sm + OFF_B2;
    float* gS  = sm + OFF_G;
    float* uvS = sm + OFF_UV;
    float* t2s = sm + OFF_T2;
    float* cpsS= sm + OFF_CP;
    float* cmsS= sm + OFF_CM;
    float* redS= sm + OFF_RED;

    const int tid  = threadIdx.x;
    const int lane = tid & 31;
    const int warp = tid >> 5;
    const int n0   = blockIdx.x * PTS_PER_CTA;

    // ---- stage weights (vectorized) / inputs ----
    {
        const float4* W2v = (const float4*)W2;
        float4* W2sv = (float4*)W2s;
        #pragma unroll
        for (int it = 0; it < 16; ++it)
            W2sv[tid + it * THREADS] = W2v[tid + it * THREADS];
        if (tid < 128) {
            ((float4*)W1s)[tid] = ((const float4*)W1)[tid];
            ((float4*)b2s)[tid] = ((const float4*)b2)[tid];
        }
        if (tid < 64) b1s[tid] = b1[tid];
        if (tid < PTS_PER_CTA * 16) {
            int pp = tid >> 4, q = tid & 15;
            uvS[tid] = (q < 8) ? uu_g[(n0 + pp) * 8 + q]
                               : vv_g[(n0 + pp) * 8 + (q - 8)];
        }
    }
    // metric g (unamplified; any fp32 order ok)
    if (tid < 512) {
        int pp = tid >> 6, ij = tid & 63, i = ij >> 3, j = ij & 7;
        int mm = (i < j) ? i : j;
        float acc = (i == j) ? 1e-6f : 0.0f;
        for (int m = 0; m <= mm; ++m)
            acc = fmaf(chol[pp * 64 + i * 8 + m], chol[pp * 64 + j * 8 + m], acc);
        gS[tid] = acc;
    }
    __syncthreads();

    // ---- Phase 1: t = fast_tanh((pos +- eps e_k)@W1 + b1), replicated rounding ----
    {
        const int p1 = warp >> 2;         // 4 warps per point
        const int q  = warp & 3;          // each warp does 4 of the 16 m's
        const int n  = n0 + p1;
        float posr[D];
        #pragma unroll
        for (int j = 0; j < D; ++j) posr[j] = pos[n * 8 + j];
        const int h0 = lane, h1 = lane + 32;
        const float bb0 = b1s[h0], bb1 = b1s[h1];
        #pragma unroll
        for (int mm = 0; mm < 4; ++mm) {
            int m = q * 4 + mm;           // m = k*2 + s; s=0 -> +eps, s=1 -> -eps
            int k = m >> 1;
            float sgn = (m & 1) ? -EPSF : EPSF;
            float acc0 = 0.0f, acc1 = 0.0f;
            #pragma unroll
            for (int j = 0; j < D; ++j) {
                float pj = posr[j];
                if (j == k) pj = __fadd_rn(pj, sgn);     // pos + offs, one rounding
                acc0 = fmaf(pj, W1s[j * 64 + h0], acc0); // ascending-j fma chain
                acc1 = fmaf(pj, W1s[j * 64 + h1], acc1);
            }
            float t0 = xla_tanh(__fadd_rn(acc0, bb0));
            float t1 = xla_tanh(__fadd_rn(acc1, bb1));
            t2s[((p1 * 64 + h0) * 8 + k) * 2 + (m & 1)] = t0;
            t2s[((p1 * 64 + h1) * 8 + k) * 2 + (m & 1)] = t1;
        }
    }
    __syncthreads();

    // ---- ownership: 128 threads per point; thread owns 4 outputs, ALL 8 k ----
    const int p    = warp >> 2;
    const int slot = tid & 127;                 // o = slot*4 + r
    const int obase = slot * 4;
    const int ii = slot >> 4;                   // c[i][a][b]
    const int aa = (slot >> 1) & 7;
    const int b0 = (slot & 1) * 4;
    const float RECIP = 1.0f / TWOEPSF;         // rn(1/2e-4); unamplified use only
    float cr[4];                                // u_i * u_a * v_b / (2eps)
    {
        float base = uvS[p * 16 + ii] * uvS[p * 16 + aa] * RECIP;
        #pragma unroll
        for (int r = 0; r < 4; ++r) cr[r] = base * uvS[p * 16 + 8 + b0 + r];
    }

    // ---- Phase 2: single pass over h; acc2[k][r] = packed (c+ , c-) ----
    u64 acc2[8][4];
    #pragma unroll
    for (int k = 0; k < 8; ++k)
        #pragma unroll
        for (int r = 0; r < 4; ++r) acc2[k][r] = 0ull;

    #pragma unroll 4
    for (int h = 0; h < HID; ++h) {
        const float4 w = *(const float4*)(W2s + h * 512 + obase);
        u64 w2d[4];
        w2d[0] = pack2(w.x, w.x); w2d[1] = pack2(w.y, w.y);
        w2d[2] = pack2(w.z, w.z); w2d[3] = pack2(w.w, w.w);
        const float4* tq = (const float4*)(t2s + p * 1024 + h * 16); // uniform
        u64 tv[8];
        #pragma unroll
        for (int kq = 0; kq < 4; ++kq) {
            float4 t4 = tq[kq];
            tv[kq * 2]     = pack2(t4.x, t4.y);
            tv[kq * 2 + 1] = pack2(t4.z, t4.w);
        }
        #pragma unroll
        for (int k = 0; k < 8; ++k)
            #pragma unroll
            for (int r = 0; r < 4; ++r)
                asm("fma.rn.f32x2 %0, %1, %2, %0;"
                    : "+l"(acc2[k][r]) : "l"(tv[k]), "l"(w2d[r]));
    }
    {   // + b2: one rounded add per element (ref rounding)
        const float4 bq = *(const float4*)(b2s + obase);
        float bv[4] = {bq.x, bq.y, bq.z, bq.w};
        #pragma unroll
        for (int r = 0; r < 4; ++r) {
            u64 bb2 = pack2(bv[r], bv[r]);
            #pragma unroll
            for (int k = 0; k < 8; ++k)
                asm("add.rn.f32x2 %0, %1, %2;"
                    : "=l"(acc2[k][r]) : "l"(acc2[k][r]), "l"(bb2));
        }
    }

    // ---- Phase 3: per-k symmetrize (own regs + smem transpose), FD, contract ----
    float partial = 0.0f;
    float* wrp = cpsS + p * 544 + ii * 68 + aa * 8 + b0;   // own (i,a,b0..b0+3)
    float* wrm = cmsS + p * 544 + ii * 68 + aa * 8 + b0;
    const float* rdp = cpsS + p * 544 + ii * 68 + b0 * 8 + aa; // partner (i,b,a)
    const float* rdm = cmsS + p * 544 + ii * 68 + b0 * 8 + aa;

    #pragma unroll
    for (int k = 0; k < 8; ++k) {
        float cp4[4], cm4[4];
        #pragma unroll
        for (int r = 0; r < 4; ++r)
            asm("mov.b64 {%0,%1}, %2;"
                : "=f"(cp4[r]), "=f"(cm4[r]) : "l"(acc2[k][r]));
        *(float4*)wrp = make_float4(cp4[0], cp4[1], cp4[2], cp4[3]);
        *(float4*)wrm = make_float4(cm4[0], cm4[1], cm4[2], cm4[3]);
        __syncthreads();
        const float vk = uvS[p * 16 + 8 + k];
        float sk = 0.0f;
        #pragma unroll
        for (int r = 0; r < 4; ++r) {
            if (b0 + r != k) {                   // (1 - eye) mask on (k, b)
                float tp = rdp[r * 8];           // c(i,b,a) at +eps
                float tm = rdm[r * 8];
                float gp = 0.5f * __fadd_rn(cp4[r], tp);   // Gamma+ (rounded)
                float gm = 0.5f * __fadd_rn(cm4[r], tm);   // Gamma-
                sk = fmaf(cr[r], __fsub_rn(gp, gm), sk);
            }
        }
        partial = fmaf(vk, sk, partial);
        __syncthreads();
    }

    // ---- reduce 128 threads per point, finalize ----
    #pragma unroll
    for (int s = 16; s; s >>= 1) partial += __shfl_xor_sync(0xffffffffu, partial, s);
    if (lane == 0) redS[warp] = partial;
    __syncthreads();
    if (tid < PTS_PER_CTA) {
        float R = (redS[4 * tid] + redS[4 * tid + 1])
                + (redS[4 * tid + 2] + redS[4 * tid + 3]);
        const int n = n0 + tid;
        const float* g = gS + (n & 7) * 64;
        const float* uL = uvS + tid * 16;
        const float* vL = uvS + tid * 16 + 8;
        float guu = 0.0f, gvv = 0.0f, guv = 0.0f;
        #pragma unroll
        for (int i = 0; i < D; ++i) {
            float gu = 0.0f, gv = 0.0f;
            #pragma unroll
            for (int j = 0; j < D; ++j) {
                float ge = g[i * 8 + j];
                gu = fmaf(ge, uL[j], gu);
                gv = fmaf(ge, vL[j], gv);
            }
            guu = fmaf(uL[i], gu, guu);
            gvv = fmaf(vL[i], gv, gvv);
            guv = fmaf(uL[i], gv, guv);
        }
        float den = fmaxf(guu * gvv - guv * guv, 1e-8f);
        out[n] = R / den;
    }
}

extern "C" void kernel_launch(void* const* d_in, const int* in_sizes, int n_in,
                              void* d_out, int out_size)
{
    const float* positions = (const float*)d_in[0];
    const float* u         = (const float*)d_in[1];
    const float* v         = (const float*)d_in[2];
    const float* chol      = (const float*)d_in[3];
    const float* W1        = (const float*)d_in[4];
    const float* b1        = (const float*)d_in[5];
    const float* W2        = (const float*)d_in[6];
    const float* b2        = (const float*)d_in[7];
    float* out = (float*)d_out;

    cudaFuncSetAttribute(rg_kernel, cudaFuncAttributeMaxDynamicSharedMemorySize,
                         SMEM_BYTES);
    rg_kernel<<<GRID, THREADS, SMEM_BYTES>>>(positions, u, v, chol,
                                             W1, b1, W2, b2, out);
}

// round 7
// speedup vs baseline: 1.2321x; 1.2321x over previous
#include <cuda_runtime.h>
#include <math.h>

#define D 8
#define HID 64
#define PTS_PER_CTA 8
#define THREADS 256
#define GRID 1024
#define EPSF 1e-4f
#define TWOEPSF 2e-4f

typedef unsigned long long u64;

__device__ __forceinline__ u64 pack2(float lo, float hi) {
    u64 r; asm("mov.b64 %0, {%1, %2};" : "=l"(r) : "f"(lo), "f"(hi)); return r;
}

// XLA EmitFastTanh (with_fma=true): verified bit-match with reference in R3.
__device__ __forceinline__ float xla_tanh(float x) {
    const float kClamp = 7.90531110763549805f;
    float xc = fminf(fmaxf(x, -kClamp), kClamp);
    float x2 = __fmul_rn(xc, xc);
    float num = -2.76076847742355e-16f;
    num = __fmaf_rn(x2, num,  2.00018790482477e-13f);
    num = __fmaf_rn(x2, num, -8.60467152213735e-11f);
    num = __fmaf_rn(x2, num,  5.12229709037114e-08f);
    num = __fmaf_rn(x2, num,  1.48572235717979e-05f);
    num = __fmaf_rn(x2, num,  6.37261928875436e-04f);
    num = __fmaf_rn(x2, num,  4.89352455891786e-03f);
    num = __fmul_rn(xc, num);
    float den = 1.19825839466702e-06f;
    den = __fmaf_rn(x2, den,  1.18534705686654e-04f);
    den = __fmaf_rn(x2, den,  2.26843463243900e-03f);
    den = __fmaf_rn(x2, den,  4.89352518554385e-03f);
    float r = __fdiv_rn(num, den);
    return (fabsf(x) < 0.0004f) ? x : r;
}

// smem float offsets
#define OFF_W2  0                        // 32768
#define OFF_W1  (OFF_W2 + 32768)         // 512
#define OFF_B1  (OFF_W1 + 512)           // 64
#define OFF_B2  (OFF_B1 + 64)            // 512
#define OFF_G   (OFF_B2 + 512)           // 512
#define OFF_UV  (OFF_G + 512)            // 8*16 = 128
#define OFF_T2  (OFF_UV + 128)           // 8 pts * 64h * 8k * 2 = 8192
#define OFF_CP  (OFF_T2 + 8192)          // 8 pts * 576 = 4608 (stride-9 pad)
#define OFF_CM  (OFF_CP + 4608)          // 4608
#define OFF_RED (OFF_CM + 4608)          // 16
#define SMEM_FLOATS (OFF_RED + 16)
#define SMEM_BYTES (SMEM_FLOATS * 4)

__global__ void __launch_bounds__(THREADS, 1)
rg_kernel(const float* __restrict__ pos, const float* __restrict__ uu_g,
          const float* __restrict__ vv_g, const float* __restrict__ chol,
          const float* __restrict__ W1,  const float* __restrict__ b1,
          const float* __restrict__ W2,  const float* __restrict__ b2,
          float* __restrict__ out)
{
    extern __shared__ float sm[];
    float* W2s = sm + OFF_W2;
    float* W1s = sm + OFF_W1;
    float* b1s = sm + OFF_B1;
    float* b2s = sm + OFF_B2;
    float* gS  = sm + OFF_G;
    float* uvS = sm + OFF_UV;
    float* t2s = sm + OFF_T2;
    float* cpsS= sm + OFF_CP;
    float* cmsS= sm + OFF_CM;
    float* redS= sm + OFF_RED;

    const int tid  = threadIdx.x;
    const int lane = tid & 31;
    const int warp = tid >> 5;
    const int n0   = blockIdx.x * PTS_PER_CTA;

    // ---- stage weights (vectorized) / inputs ----
    {
        const float4* W2v = (const float4*)W2;
        float4* W2sv = (float4*)W2s;
        #pragma unroll
        for (int it = 0; it < 32; ++it)
            W2sv[tid + it * THREADS] = W2v[tid + it * THREADS];
        if (tid < 128) {
            ((float4*)W1s)[tid] = ((const float4*)W1)[tid];
            ((float4*)b2s)[tid] = ((const float4*)b2)[tid];
        }
        if (tid < 64) b1s[tid] = b1[tid];
        if (tid < PTS_PER_CTA * 16) {
            int pp = tid >> 4, q = tid & 15;
            uvS[tid] = (q < 8) ? uu_g[(n0 + pp) * 8 + q]
                               : vv_g[(n0 + pp) * 8 + (q - 8)];
        }
    }
    // metric g (unamplified; any fp32 order ok)
    for (int idx = tid; idx < 512; idx += THREADS) {
        int pp = idx >> 6, ij = idx & 63, i = ij >> 3, j = ij & 7;
        int mm = (i < j) ? i : j;
        float acc = (i == j) ? 1e-6f : 0.0f;
        for (int m = 0; m <= mm; ++m)
            acc = fmaf(chol[pp * 64 + i * 8 + m], chol[pp * 64 + j * 8 + m], acc);
        gS[idx] = acc;
    }
    __syncthreads();

    // ---- Phase 1: one warp per point; t = fast_tanh((pos +- eps e_k)@W1 + b1) ----
    {
        const int p1 = warp;              // 8 warps, 8 points
        const int n  = n0 + p1;
        float posr[D];
        #pragma unroll
        for (int j = 0; j < D; ++j) posr[j] = pos[n * 8 + j];
        const int h0 = lane, h1 = lane + 32;
        const float bb0 = b1s[h0], bb1 = b1s[h1];
        #pragma unroll
        for (int m = 0; m < 16; ++m) {    // m = k*2 + s; s=0 -> +eps, s=1 -> -eps
            int k = m >> 1;
            float sgn = (m & 1) ? -EPSF : EPSF;
            float acc0 = 0.0f, acc1 = 0.0f;
            #pragma unroll
            for (int j = 0; j < D; ++j) {
                float pj = posr[j];
                if (j == k) pj = __fadd_rn(pj, sgn);     // pos + offs, one rounding
                acc0 = fmaf(pj, W1s[j * 64 + h0], acc0); // ascending-j fma chain
                acc1 = fmaf(pj, W1s[j * 64 + h1], acc1);
            }
            float t0 = xla_tanh(__fadd_rn(acc0, bb0));
            float t1 = xla_tanh(__fadd_rn(acc1, bb1));
            t2s[((p1 * 64 + h0) * 8 + k) * 2 + (m & 1)] = t0;
            t2s[((p1 * 64 + h1) * 8 + k) * 2 + (m & 1)] = t1;
        }
    }
    __syncthreads();

    // ---- ownership: thread handles 2 points (pA, pB), 8 consecutive outputs ----
    const int pair = tid >> 6;               // 0..3
    const int slot = tid & 63;               // i = slot>>3, j = slot&7
    const int pA   = 2 * pair, pB = 2 * pair + 1;
    const int obase = slot * 8;
    const float RECIP = 1.0f / TWOEPSF;      // rn(1/2e-4); unamplified use only
    float wlA[8], wlB[8];                    // u_i*u_j*v_l/(2eps) per point
    {
        int i = slot >> 3, j = slot & 7;
        float wa = uvS[pA * 16 + i] * uvS[pA * 16 + j] * RECIP;
        float wb = uvS[pB * 16 + i] * uvS[pB * 16 + j] * RECIP;
        #pragma unroll
        for (int l = 0; l < 8; ++l) {
            wlA[l] = wa * uvS[pA * 16 + 8 + l];
            wlB[l] = wb * uvS[pB * 16 + 8 + l];
        }
    }

    float partialA = 0.0f, partialB = 0.0f;
    const u64* t2uA = reinterpret_cast<const u64*>(t2s) + pA * 512;  // [h*8 + k]
    const u64* t2uB = reinterpret_cast<const u64*>(t2s) + pB * 512;
    const int rdoff = (slot & 0x38) * 9 + (slot & 7);
    float* wrpA = cpsS + pA * 576 + slot * 9;
    float* wrmA = cmsS + pA * 576 + slot * 9;
    float* wrpB = cpsS + pB * 576 + slot * 9;
    float* wrmB = cmsS + pB * 576 + slot * 9;

    #pragma unroll
    for (int g = 0; g < 2; ++g) {            // k-groups {0..3}, {4..7}
        // ---- Phase 2 (group g): ascending-h fma chains, packed +/-, 2 points ----
        u64 accA[4][8], accB[4][8];
        #pragma unroll
        for (int kk = 0; kk < 4; ++kk)
            #pragma unroll
            for (int r = 0; r < 8; ++r) { accA[kk][r] = 0ull; accB[kk][r] = 0ull; }

        #pragma unroll 2
        for (int h = 0; h < HID; ++h) {
            const float4* w2q = (const float4*)(W2s + h * 512 + obase);
            float4 wa = w2q[0], wb = w2q[1];
            u64 w2d[8];
            w2d[0] = pack2(wa.x, wa.x); w2d[1] = pack2(wa.y, wa.y);
            w2d[2] = pack2(wa.z, wa.z); w2d[3] = pack2(wa.w, wa.w);
            w2d[4] = pack2(wb.x, wb.x); w2d[5] = pack2(wb.y, wb.y);
            w2d[6] = pack2(wb.z, wb.z); w2d[7] = pack2(wb.w, wb.w);
            u64 tvA[4], tvB[4];
            #pragma unroll
            for (int kk = 0; kk < 4; ++kk) {
                tvA[kk] = t2uA[h * 8 + g * 4 + kk];   // uniform broadcast loads
                tvB[kk] = t2uB[h * 8 + g * 4 + kk];
            }
            #pragma unroll
            for (int kk = 0; kk < 4; ++kk)
                #pragma unroll
                for (int r = 0; r < 8; ++r) {
                    asm("fma.rn.f32x2 %0, %1, %2, %0;"
                        : "+l"(accA[kk][r]) : "l"(tvA[kk]), "l"(w2d[r]));
                    asm("fma.rn.f32x2 %0, %1, %2, %0;"
                        : "+l"(accB[kk][r]) : "l"(tvB[kk]), "l"(w2d[r]));
                }
        }
        {   // + b2: one rounded add per element
            const float4* b2q = (const float4*)(b2s + obase);
            float4 ba = b2q[0], bb = b2q[1];
            float bv[8] = {ba.x, ba.y, ba.z, ba.w, bb.x, bb.y, bb.z, bb.w};
            #pragma unroll
            for (int r = 0; r < 8; ++r) {
                u64 bb2 = pack2(bv[r], bv[r]);
                #pragma unroll
                for (int kk = 0; kk < 4; ++kk) {
                    asm("add.rn.f32x2 %0, %1, %2;"
                        : "=l"(accA[kk][r]) : "l"(accA[kk][r]), "l"(bb2));
                    asm("add.rn.f32x2 %0, %1, %2;"
                        : "=l"(accB[kk][r]) : "l"(accB[kk][r]), "l"(bb2));
                }
            }
        }

        // ---- Phase 3 (group g): per-k symmetrize (own regs + smem transpose), FD ----
        #pragma unroll
        for (int kk = 0; kk < 4; ++kk) {
            const int k = g * 4 + kk;
            float cpA[8], cmA[8], cpB[8], cmB[8];
            #pragma unroll
            for (int r = 0; r < 8; ++r) {
                asm("mov.b64 {%0,%1}, %2;"
                    : "=f"(cpA[r]), "=f"(cmA[r]) : "l"(accA[kk][r]));
                asm("mov.b64 {%0,%1}, %2;"
                    : "=f"(cpB[r]), "=f"(cmB[r]) : "l"(accB[kk][r]));
                wrpA[r] = cpA[r]; wrmA[r] = cmA[r];   // 9*slot mod 32 unique
                wrpB[r] = cpB[r]; wrmB[r] = cmB[r];
            }
            __syncthreads();
            const float vkA = uvS[pA * 16 + 8 + k];
            const float vkB = uvS[pB * 16 + 8 + k];
            float skA = 0.0f, skB = 0.0f;
            const float* rpA = cpsS + pA * 576 + rdoff;
            const float* rmA = cmsS + pA * 576 + rdoff;
            const float* rpB = cpsS + pB * 576 + rdoff;
            const float* rmB = cmsS + pB * 576 + rdoff;
            #pragma unroll
            for (int l = 0; l < 8; ++l) {
                if (l == k) continue;              // (1 - eye) mask on (k,l)
                float gpA = 0.5f * __fadd_rn(cpA[l], rpA[l * 9]);
                float gmA = 0.5f * __fadd_rn(cmA[l], rmA[l * 9]);
                skA = fmaf(wlA[l], __fsub_rn(gpA, gmA), skA);
                float gpB = 0.5f * __fadd_rn(cpB[l], rpB[l * 9]);
                float gmB = 0.5f * __fadd_rn(cmB[l], rmB[l * 9]);
                skB = fmaf(wlB[l], __fsub_rn(gpB, gmB), skB);
            }
            partialA = fmaf(vkA, skA, partialA);
            partialB = fmaf(vkB, skB, partialB);
            __syncthreads();
        }
    }

    // ---- reduce: 64 threads (2 warps) per point-pair ----
    #pragma unroll
    for (int s = 16; s; s >>= 1) {
        partialA += __shfl_xor_sync(0xffffffffu, partialA, s);
        partialB += __shfl_xor_sync(0xffffffffu, partialB, s);
    }
    if (lane == 0) { redS[warp * 2] = partialA; redS[warp * 2 + 1] = partialB; }
    __syncthreads();
    if (tid < PTS_PER_CTA) {
        const int p = tid;
        const int w0 = 2 * (p >> 1);
        float R = redS[w0 * 2 + (p & 1)] + redS[(w0 + 1) * 2 + (p & 1)];
        const int n = n0 + p;
        const float* g = gS + (n & 7) * 64;
        const float* uL = uvS + p * 16;
        const float* vL = uvS + p * 16 + 8;
        float guu = 0.0f, gvv = 0.0f, guv = 0.0f;
        #pragma unroll
        for (int i = 0; i < D; ++i) {
            float gu = 0.0f, gv = 0.0f;
            #pragma unroll
            for (int j = 0; j < D; ++j) {
                float ge = g[i * 8 + j];
                gu = fmaf(ge, uL[j], gu);
                gv = fmaf(ge, vL[j], gv);
            }
            guu = fmaf(uL[i], gu, guu);
            gvv = fmaf(vL[i], gv, gvv);
            guv = fmaf(uL[i], gv, guv);
        }
        float den = fmaxf(guu * gvv - guv * guv, 1e-8f);
        out[n] = R / den;
    }
}

extern "C" void kernel_launch(void* const* d_in, const int* in_sizes, int n_in,
                              void* d_out, int out_size)
{
    const float* positions = (const float*)d_in[0];
    const float* u         = (const float*)d_in[1];
    const float* v         = (const float*)d_in[2];
    const float* chol      = (const float*)d_in[3];
    const float* W1        = (const float*)d_in[4];
    const float* b1        = (const float*)d_in[5];
    const float* W2        = (const float*)d_in[6];
    const float* b2        = (const float*)d_in[7];
    float* out = (float*)d_out;

    cudaFuncSetAttribute(rg_kernel, cudaFuncAttributeMaxDynamicSharedMemorySize,
                         SMEM_BYTES);
    rg_kernel<<<GRID, THREADS, SMEM_BYTES>>>(positions, u, v, chol,
                                             W1, b1, W2, b2, out);
}